// round 16
// baseline (speedup 1.0000x reference)
#include <cuda_runtime.h>
#include <cstdint>

#define HIDDEN   5120
#define NEXP     160
#define NGROUP   8
#define EPG      20
#define TOPK     6

#define BM       64
#define BK       16
#define NCHUNK   (HIDDEN / BK)   // 320
#define NTHREADS 256
#define LSTR     161

// A-only smem chunk: 4 m16 tiles x [hi 512B | lo 512B]
#define A_BYTES  4096
#define B_IMG    10240
#define SMEM_BYTES (BM * LSTR * 4)   // 41216 >= 2*A_BYTES

#define NEG_INF (-__int_as_float(0x7f800000))
#define DELTA   3e-5f

__device__ int   g_count;
__device__ int   g_list[16384];
__device__ float g_W2[NCHUNK * B_IMG / 4];   // 3.28 MB bf16-split frag images

__device__ __forceinline__ void mma_bf16(float* d, const uint32_t* a,
                                         uint32_t b0, uint32_t b1) {
    asm volatile(
        "mma.sync.aligned.m16n8k16.row.col.f32.bf16.bf16.f32 "
        "{%0,%1,%2,%3},{%4,%5,%6,%7},{%8,%9},{%0,%1,%2,%3};"
        : "+f"(d[0]), "+f"(d[1]), "+f"(d[2]), "+f"(d[3])
        : "r"(a[0]), "r"(a[1]), "r"(a[2]), "r"(a[3]), "r"(b0), "r"(b1));
}

__device__ __forceinline__ uint32_t packbf(float lo_elem, float hi_elem) {
    uint32_t r;
    asm("cvt.rn.bf16x2.f32 %0, %1, %2;" : "=r"(r) : "f"(hi_elem), "f"(lo_elem));
    return r;
}

__device__ __forceinline__ void split_pair(float e0, float e1,
                                           uint32_t& hi, uint32_t& lo) {
    hi = packbf(e0, e1);
    const float h0 = __uint_as_float(hi << 16);
    const float h1 = __uint_as_float(hi & 0xFFFF0000u);
    lo = packbf(e0 - h0, e1 - h1);
}

// stage one A float4: (row, k = q*4 + t); row in 0..63
__device__ __forceinline__ void stage_f4A(char* buf, int row, int q, float4 v) {
    char* tb = buf + (row >> 4) * 1024;
    const int reg = ((row & 15) >> 3) + (q >> 1) * 2;
    const int lbase = (row & 7) * 4 + (q & 1) * 2;
#pragma unroll
    for (int p = 0; p < 2; p++) {
        const float e0 = p ? v.z : v.x;
        const float e1 = p ? v.w : v.y;
        uint32_t hi, lo;
        split_pair(e0, e1, hi, lo);
        char* s = tb + (lbase + p) * 16 + reg * 4;
        *(uint32_t*)s = hi;
        *(uint32_t*)(s + 512) = lo;
    }
}

// ---- W prep (also resets flag counter) ----
extern "C" __global__ void __launch_bounds__(256, 1)
prep_kernel(const float* __restrict__ W)
{
    const int idx = blockIdx.x * 256 + threadIdx.x;
    if (idx == 0) g_count = 0;
    if (idx >= NCHUNK * NEXP * 4) return;
    const int c = idx / (NEXP * 4);
    const int r = idx % (NEXP * 4);
    const int n = r >> 2;
    const int q = r & 3;

    const float4 v = *(const float4*)(W + (size_t)n * HIDDEN + c * BK + q * 4);
    char* img = (char*)g_W2 + (size_t)c * B_IMG + (n >> 3) * 512;
    const int lbase = (n & 7) * 4 + (q & 1) * 2;
    const int kq = q >> 1;
#pragma unroll
    for (int p = 0; p < 2; p++) {
        const float e0 = p ? v.z : v.x;
        const float e1 = p ? v.w : v.y;
        uint32_t hi, lo;
        split_pair(e0, e1, hi, lo);
        char* s = img + (lbase + p) * 16 + kq * 4;
        *(uint32_t*)s = hi;
        *(uint32_t*)(s + 8) = lo;
    }
}

// ---- gating (verified), returns min decision margin ----
__device__ __forceinline__ float do_gate(const float* row, float* outIdx,
                                         float* outW, size_t base) {
    float gmax[NGROUP];
    float m = NEG_INF;
#pragma unroll
    for (int g = 0; g < NGROUP; g++) {
        float gm = NEG_INF;
#pragma unroll
        for (int j = 0; j < EPG; j++)
            gm = fmaxf(gm, row[g * EPG + j]);
        gmax[g] = gm;
        m = fmaxf(m, gm);
    }

    float v0 = NEG_INF, v1 = NEG_INF, v2 = NEG_INF;
    int g0 = 0, g1 = 0, g2 = 0;
#pragma unroll
    for (int g = 0; g < NGROUP; g++) {
        const float v = gmax[g];
        if (v > v0)      { v2 = v1; g2 = g1; v1 = v0; g1 = g0; v0 = v; g0 = g; }
        else if (v > v1) { v2 = v1; g2 = g1; v1 = v;  g1 = g; }
        else if (v > v2) { v2 = v;  g2 = g; }
    }
    const unsigned gm_mask = (1u << g0) | (1u << g1) | (1u << g2);

    float v3 = NEG_INF;
#pragma unroll
    for (int g = 0; g < NGROUP; g++)
        if (!((gm_mask >> g) & 1u)) v3 = fmaxf(v3, gmax[g]);

    float tv0 = NEG_INF, tv1 = NEG_INF, tv2 = NEG_INF;
    float tv3 = NEG_INF, tv4 = NEG_INF, tv5 = NEG_INF;
    int ti0 = -1, ti1 = -1, ti2 = -1, ti3 = -1, ti4 = -1, ti5 = -1;
#pragma unroll 1
    for (int g = 0; g < NGROUP; g++) {
        if (!((gm_mask >> g) & 1u)) continue;
#pragma unroll 1
        for (int j = 0; j < EPG; j++) {
            const int e = g * EPG + j;
            const float v = row[e];
            if (v > tv5) {
                if (v > tv4) { tv5 = tv4; ti5 = ti4;
                    if (v > tv3) { tv4 = tv3; ti4 = ti3;
                        if (v > tv2) { tv3 = tv2; ti3 = ti2;
                            if (v > tv1) { tv2 = tv1; ti2 = ti1;
                                if (v > tv0) { tv1 = tv0; ti1 = ti0; tv0 = v; ti0 = e; }
                                else          { tv1 = v;  ti1 = e; }
                            } else { tv2 = v; ti2 = e; }
                        } else { tv3 = v; ti3 = e; }
                    } else { tv4 = v; ti4 = e; }
                } else { tv5 = v; ti5 = e; }
            }
        }
    }

    float tv6 = NEG_INF;
#pragma unroll 1
    for (int g = 0; g < NGROUP; g++) {
        if (!((gm_mask >> g) & 1u)) continue;
#pragma unroll 1
        for (int j = 0; j < EPG; j++) {
            const int e = g * EPG + j;
            const float v = row[e];
            if (v > tv6 &&
                e != ti0 && e != ti1 && e != ti2 &&
                e != ti3 && e != ti4 && e != ti5) tv6 = v;
        }
    }

    const float w0 = expf(tv0 - m), w1 = expf(tv1 - m), w2 = expf(tv2 - m);
    const float w3 = expf(tv3 - m), w4 = expf(tv4 - m), w5 = expf(tv5 - m);
    const float inv = 1.0f / (w0 + w1 + w2 + w3 + w4 + w5 + 1e-20f);

    outIdx[base + 0] = (float)ti0;  outW[base + 0] = w0 * inv;
    outIdx[base + 1] = (float)ti1;  outW[base + 1] = w1 * inv;
    outIdx[base + 2] = (float)ti2;  outW[base + 2] = w2 * inv;
    outIdx[base + 3] = (float)ti3;  outW[base + 3] = w3 * inv;
    outIdx[base + 4] = (float)ti4;  outW[base + 4] = w4 * inv;
    outIdx[base + 5] = (float)ti5;  outW[base + 5] = w5 * inv;

    float mg = v2 - v3;
    mg = fminf(mg, tv0 - tv1);
    mg = fminf(mg, tv1 - tv2);
    mg = fminf(mg, tv2 - tv3);
    mg = fminf(mg, tv3 - tv4);
    mg = fminf(mg, tv4 - tv5);
    mg = fminf(mg, tv5 - tv6);
    return mg;
}

extern "C" __global__ void __launch_bounds__(NTHREADS, 2)
moe_gate_kernel(const float* __restrict__ X,
                float* __restrict__ out, int T)
{
    extern __shared__ char smem[];
    float* logits = (float*)smem;

    const int tid  = threadIdx.x;
    const int wid  = tid >> 5;
    const int lane = tid & 31;
    const int wm   = wid >> 2;     // 0..1 : 32 token rows each
    const int wn   = wid & 3;      // 0..3 : 40 expert cols
    const int row0 = blockIdx.x * BM;

    float acc[2][5][4];
#pragma unroll
    for (int i = 0; i < 2; i++)
#pragma unroll
        for (int j = 0; j < 5; j++)
#pragma unroll
            for (int r = 0; r < 4; r++) acc[i][j][r] = 0.0f;

    const int a0r = tid >> 2, a0q = tid & 3;
    const float* Ap0 = X + (size_t)(row0 + a0r) * HIDDEN + a0q * 4;

    // this warp's B-fragment gmem base (lane-coalesced LDG.128)
    const char* Bg = (const char*)g_W2 + (wn * 5) * 512 + lane * 16;

    // prologue: stage A(0), prefetch A(1), load B frags(0)
    float4 fa = *(const float4*)(Ap0);
    stage_f4A((char*)smem, a0r, a0q, fa);
    fa = *(const float4*)(Ap0 + BK);

    uint4 bfc[5], bfn[5];
#pragma unroll
    for (int j = 0; j < 5; j++)
        bfc[j] = *(const uint4*)(Bg + j * 512);

    for (int c = 0; c < NCHUNK; ++c) {
        // A(c) visible to all; every thread done with compute(c-1)
        __syncthreads();

        if (c + 1 < NCHUNK) {
            // stage A(c+1) into the other buffer
            stage_f4A((char*)smem + ((c + 1) & 1) * A_BYTES, a0r, a0q, fa);
            if (c + 2 < NCHUNK)
                fa = *(const float4*)(Ap0 + (c + 2) * BK);
            // prefetch B frags(c+1) into regs (covers L2 latency)
            const char* src = Bg + (size_t)(c + 1) * B_IMG;
#pragma unroll
            for (int j = 0; j < 5; j++)
                bfn[j] = *(const uint4*)(src + j * 512);
        }

        // compute chunk c: A from smem buf[c&1], B from bfc regs
        {
            const char* ab = (char*)smem + (c & 1) * A_BYTES;

            uint4 ah[2], al[2];
#pragma unroll
            for (int i = 0; i < 2; i++) {
                const char* tb = ab + (wm * 2 + i) * 1024 + lane * 16;
                ah[i] = *(const uint4*)(tb);
                al[i] = *(const uint4*)(tb + 512);
            }

#pragma unroll
            for (int i = 0; i < 2; i++) {
                const uint32_t ar[4] = {ah[i].x, ah[i].y, ah[i].z, ah[i].w};
#pragma unroll
                for (int j = 0; j < 5; j++)
                    mma_bf16(acc[i][j], ar, bfc[j].x, bfc[j].y);   // hi*hi
            }
#pragma unroll
            for (int i = 0; i < 2; i++) {
                const uint32_t ar[4] = {ah[i].x, ah[i].y, ah[i].z, ah[i].w};
#pragma unroll
                for (int j = 0; j < 5; j++)
                    mma_bf16(acc[i][j], ar, bfc[j].z, bfc[j].w);   // hi*lo
            }
#pragma unroll
            for (int i = 0; i < 2; i++) {
                const uint32_t ar[4] = {al[i].x, al[i].y, al[i].z, al[i].w};
#pragma unroll
                for (int j = 0; j < 5; j++)
                    mma_bf16(acc[i][j], ar, bfc[j].x, bfc[j].y);   // lo*hi
            }
        }

        if (c + 1 < NCHUNK) {
#pragma unroll
            for (int j = 0; j < 5; j++) bfc[j] = bfn[j];
        }
    }

    __syncthreads();
    {
        const int g = lane >> 2, t = lane & 3;
#pragma unroll
        for (int i = 0; i < 2; i++) {
#pragma unroll
            for (int j = 0; j < 5; j++) {
                float* lrow = logits + (wm * 32 + i * 16 + g) * LSTR
                                     + wn * 40 + j * 8 + t * 2;
                lrow[0] = acc[i][j][0];
                lrow[1] = acc[i][j][1];
                lrow[8 * LSTR + 0] = acc[i][j][2];
                lrow[8 * LSTR + 1] = acc[i][j][3];
            }
        }
    }
    __syncthreads();

    if (tid < BM) {
        const int t = row0 + tid;
        if (t < T) {
            const float mg = do_gate(logits + tid * LSTR,
                                     out, out + (size_t)T * TOPK,
                                     (size_t)t * TOPK);
            if (mg < DELTA) {
                const int slot = atomicAdd(&g_count, 1);
                g_list[slot] = t;
            }
        }
    }
}

// ---- rescue v2 (verified): warp-parallel exact-fp32 recompute ----
extern "C" __global__ void __launch_bounds__(256, 1)
refine_kernel(const float* __restrict__ X,
              const float* __restrict__ W,
              float* __restrict__ out, int T)
{
    __shared__ float4 xs4[HIDDEN / 4];
    __shared__ float  lg[NEXP];

    const int tid  = threadIdx.x;
    const int wid  = tid >> 5;
    const int lane = tid & 31;

    const int count = g_count;
    for (int i = blockIdx.x; i < count; i += gridDim.x) {
        const int t = g_list[i];
        const float4* xr = (const float4*)(X + (size_t)t * HIDDEN);
#pragma unroll
        for (int j = 0; j < 5; j++)
            xs4[tid + j * 256] = xr[tid + j * 256];
        __syncthreads();

#pragma unroll 1
        for (int el = 0; el < EPG; el++) {
            const int e = wid * EPG + el;
            const float4* wr = (const float4*)(W + (size_t)e * HIDDEN);
            float s0 = 0.0f, s1 = 0.0f;
#pragma unroll
            for (int j = 0; j < 40; j += 2) {
                const float4 u0 = wr[lane + j * 32];
                const float4 x0 = xs4[lane + j * 32];
                s0 = fmaf(u0.x, x0.x, s0);
                s0 = fmaf(u0.y, x0.y, s0);
                s0 = fmaf(u0.z, x0.z, s0);
                s0 = fmaf(u0.w, x0.w, s0);
                const float4 u1 = wr[lane + (j + 1) * 32];
                const float4 x1 = xs4[lane + (j + 1) * 32];
                s1 = fmaf(u1.x, x1.x, s1);
                s1 = fmaf(u1.y, x1.y, s1);
                s1 = fmaf(u1.z, x1.z, s1);
                s1 = fmaf(u1.w, x1.w, s1);
            }
            float s = s0 + s1;
#pragma unroll
            for (int off = 16; off > 0; off >>= 1)
                s += __shfl_xor_sync(0xFFFFFFFFu, s, off);
            if (lane == 0) lg[e] = s;
        }
        __syncthreads();

        if (tid == 0)
            do_gate(lg, out, out + (size_t)T * TOPK, (size_t)t * TOPK);
        __syncthreads();
    }
}

extern "C" void kernel_launch(void* const* d_in, const int* in_sizes, int n_in,
                              void* d_out, int out_size)
{
    const float* X = (const float*)d_in[0];
    const float* W = (const float*)d_in[1];
    const int T = in_sizes[0] / HIDDEN;   // 16384

    cudaFuncSetAttribute(moe_gate_kernel,
                         cudaFuncAttributeMaxDynamicSharedMemorySize, SMEM_BYTES);

    prep_kernel<<<(NCHUNK * NEXP * 4 + 255) / 256, 256>>>(W);
    const int grid = (T + BM - 1) / BM;   // 256
    moe_gate_kernel<<<grid, NTHREADS, SMEM_BYTES>>>(X, (float*)d_out, T);
    refine_kernel<<<148, 256>>>(X, W, (float*)d_out, T);
}

// round 17
// speedup vs baseline: 1.3366x; 1.3366x over previous
#include <cuda_runtime.h>
#include <cstdint>

#define HIDDEN   5120
#define NEXP     160
#define NGROUP   8
#define EPG      20
#define TOPK     6

#define BM       64
#define BKI      32                  // k per pipeline iteration (2 x k16)
#define NITER    (HIDDEN / BKI)      // 160
#define NTHREADS 256
#define LSTR     161

// stage layout: A (2 halves x 4096) then B (2 chunk images x 10240)
#define A_BYTES   8192
#define B_IMG     10240
#define B_BYTES   20480
#define STAGE_BYTES 28672
#define MBAR_OFF  (2 * STAGE_BYTES)            // 57344
#define SMEM_BYTES (MBAR_OFF + 32)             // 57376 >= logits 41216

#define NEG_INF (-__int_as_float(0x7f800000))
#define DELTA   3e-5f

__device__ int   g_count;
__device__ int   g_list[16384];
__device__ float g_W2[(HIDDEN / 16) * B_IMG / 4];   // 3.28 MB

__device__ __forceinline__ uint32_t smem_u32(const void* p) {
    uint32_t a;
    asm("{ .reg .u64 t; cvta.to.shared.u64 t, %1; cvt.u32.u64 %0, t; }"
        : "=r"(a) : "l"(p));
    return a;
}

__device__ __forceinline__ void mbar_init(uint32_t bar, uint32_t cnt) {
    asm volatile("mbarrier.init.shared.b64 [%0], %1;" :: "r"(bar), "r"(cnt) : "memory");
}
__device__ __forceinline__ void mbar_expect_tx(uint32_t bar, uint32_t bytes) {
    asm volatile("mbarrier.arrive.expect_tx.shared.b64 _, [%0], %1;"
                 :: "r"(bar), "r"(bytes) : "memory");
}
__device__ __forceinline__ void bulk_cp(uint32_t dst, const void* src,
                                        uint32_t bytes, uint32_t bar) {
    asm volatile(
        "cp.async.bulk.shared::cta.global.mbarrier::complete_tx::bytes "
        "[%0], [%1], %2, [%3];"
        :: "r"(dst), "l"(src), "r"(bytes), "r"(bar) : "memory");
}
__device__ __forceinline__ void mbar_wait(uint32_t bar, uint32_t parity) {
    uint32_t done;
    asm volatile("{ .reg .pred p; mbarrier.try_wait.parity.acquire.cta.shared::cta.b64 p, [%1], %2; selp.b32 %0, 1, 0, p; }"
                 : "=r"(done) : "r"(bar), "r"(parity) : "memory");
    if (!done) {
        asm volatile("{ .reg .pred P1; WL%=: mbarrier.try_wait.parity.acquire.cta.shared::cta.b64 P1, [%0], %1, 0x989680; @P1 bra.uni WD%=; bra.uni WL%=; WD%=: }"
                     :: "r"(bar), "r"(parity) : "memory");
    }
}

__device__ __forceinline__ void mma_bf16(float* d, const uint32_t* a,
                                         uint32_t b0, uint32_t b1) {
    asm volatile(
        "mma.sync.aligned.m16n8k16.row.col.f32.bf16.bf16.f32 "
        "{%0,%1,%2,%3},{%4,%5,%6,%7},{%8,%9},{%0,%1,%2,%3};"
        : "+f"(d[0]), "+f"(d[1]), "+f"(d[2]), "+f"(d[3])
        : "r"(a[0]), "r"(a[1]), "r"(a[2]), "r"(a[3]), "r"(b0), "r"(b1));
}

__device__ __forceinline__ uint32_t packbf(float lo_elem, float hi_elem) {
    uint32_t r;
    asm("cvt.rn.bf16x2.f32 %0, %1, %2;" : "=r"(r) : "f"(hi_elem), "f"(lo_elem));
    return r;
}

__device__ __forceinline__ void split_pair(float e0, float e1,
                                           uint32_t& hi, uint32_t& lo) {
    hi = packbf(e0, e1);
    const float h0 = __uint_as_float(hi << 16);
    const float h1 = __uint_as_float(hi & 0xFFFF0000u);
    lo = packbf(e0 - h0, e1 - h1);
}

// stage one A float4 within a k16 half: (row 0..63, q 0..3)
__device__ __forceinline__ void stage_f4A16(char* buf, int row, int q, float4 v) {
    char* tb = buf + (row >> 4) * 1024;
    const int reg = ((row & 15) >> 3) + (q >> 1) * 2;
    const int lbase = (row & 7) * 4 + (q & 1) * 2;
#pragma unroll
    for (int p = 0; p < 2; p++) {
        const float e0 = p ? v.z : v.x;
        const float e1 = p ? v.w : v.y;
        uint32_t hi, lo;
        split_pair(e0, e1, hi, lo);
        char* s = tb + (lbase + p) * 16 + reg * 4;
        *(uint32_t*)s = hi;
        *(uint32_t*)(s + 512) = lo;
    }
}

// q in 0..7 over a 32-k iteration: half = q>>2, inner q = q&3
__device__ __forceinline__ void stage_f4A32(char* buf, int row, int q, float4 v) {
    stage_f4A16(buf + (q >> 2) * 4096, row, q & 3, v);
}

// ---- W prep (also resets flag counter) ----
extern "C" __global__ void __launch_bounds__(256, 1)
prep_kernel(const float* __restrict__ W)
{
    const int idx = blockIdx.x * 256 + threadIdx.x;
    if (idx == 0) g_count = 0;
    if (idx >= (HIDDEN / 16) * NEXP * 4) return;
    const int c = idx / (NEXP * 4);
    const int r = idx % (NEXP * 4);
    const int n = r >> 2;
    const int q = r & 3;

    const float4 v = *(const float4*)(W + (size_t)n * HIDDEN + c * 16 + q * 4);
    char* img = (char*)g_W2 + (size_t)c * B_IMG + (n >> 3) * 512;
    const int lbase = (n & 7) * 4 + (q & 1) * 2;
    const int kq = q >> 1;
#pragma unroll
    for (int p = 0; p < 2; p++) {
        const float e0 = p ? v.z : v.x;
        const float e1 = p ? v.w : v.y;
        uint32_t hi, lo;
        split_pair(e0, e1, hi, lo);
        char* s = img + (lbase + p) * 16 + kq * 4;
        *(uint32_t*)s = hi;
        *(uint32_t*)(s + 8) = lo;
    }
}

// ---- gating (verified), returns min decision margin ----
__device__ __forceinline__ float do_gate(const float* row, float* outIdx,
                                         float* outW, size_t base) {
    float gmax[NGROUP];
    float m = NEG_INF;
#pragma unroll
    for (int g = 0; g < NGROUP; g++) {
        float gm = NEG_INF;
#pragma unroll
        for (int j = 0; j < EPG; j++)
            gm = fmaxf(gm, row[g * EPG + j]);
        gmax[g] = gm;
        m = fmaxf(m, gm);
    }

    float v0 = NEG_INF, v1 = NEG_INF, v2 = NEG_INF;
    int g0 = 0, g1 = 0, g2 = 0;
#pragma unroll
    for (int g = 0; g < NGROUP; g++) {
        const float v = gmax[g];
        if (v > v0)      { v2 = v1; g2 = g1; v1 = v0; g1 = g0; v0 = v; g0 = g; }
        else if (v > v1) { v2 = v1; g2 = g1; v1 = v;  g1 = g; }
        else if (v > v2) { v2 = v;  g2 = g; }
    }
    const unsigned gm_mask = (1u << g0) | (1u << g1) | (1u << g2);

    float v3 = NEG_INF;
#pragma unroll
    for (int g = 0; g < NGROUP; g++)
        if (!((gm_mask >> g) & 1u)) v3 = fmaxf(v3, gmax[g]);

    float tv0 = NEG_INF, tv1 = NEG_INF, tv2 = NEG_INF;
    float tv3 = NEG_INF, tv4 = NEG_INF, tv5 = NEG_INF;
    int ti0 = -1, ti1 = -1, ti2 = -1, ti3 = -1, ti4 = -1, ti5 = -1;
#pragma unroll 1
    for (int g = 0; g < NGROUP; g++) {
        if (!((gm_mask >> g) & 1u)) continue;
#pragma unroll 1
        for (int j = 0; j < EPG; j++) {
            const int e = g * EPG + j;
            const float v = row[e];
            if (v > tv5) {
                if (v > tv4) { tv5 = tv4; ti5 = ti4;
                    if (v > tv3) { tv4 = tv3; ti4 = ti3;
                        if (v > tv2) { tv3 = tv2; ti3 = ti2;
                            if (v > tv1) { tv2 = tv1; ti2 = ti1;
                                if (v > tv0) { tv1 = tv0; ti1 = ti0; tv0 = v; ti0 = e; }
                                else          { tv1 = v;  ti1 = e; }
                            } else { tv2 = v; ti2 = e; }
                        } else { tv3 = v; ti3 = e; }
                    } else { tv4 = v; ti4 = e; }
                } else { tv5 = v; ti5 = e; }
            }
        }
    }

    float tv6 = NEG_INF;
#pragma unroll 1
    for (int g = 0; g < NGROUP; g++) {
        if (!((gm_mask >> g) & 1u)) continue;
#pragma unroll 1
        for (int j = 0; j < EPG; j++) {
            const int e = g * EPG + j;
            const float v = row[e];
            if (v > tv6 &&
                e != ti0 && e != ti1 && e != ti2 &&
                e != ti3 && e != ti4 && e != ti5) tv6 = v;
        }
    }

    const float w0 = expf(tv0 - m), w1 = expf(tv1 - m), w2 = expf(tv2 - m);
    const float w3 = expf(tv3 - m), w4 = expf(tv4 - m), w5 = expf(tv5 - m);
    const float inv = 1.0f / (w0 + w1 + w2 + w3 + w4 + w5 + 1e-20f);

    outIdx[base + 0] = (float)ti0;  outW[base + 0] = w0 * inv;
    outIdx[base + 1] = (float)ti1;  outW[base + 1] = w1 * inv;
    outIdx[base + 2] = (float)ti2;  outW[base + 2] = w2 * inv;
    outIdx[base + 3] = (float)ti3;  outW[base + 3] = w3 * inv;
    outIdx[base + 4] = (float)ti4;  outW[base + 4] = w4 * inv;
    outIdx[base + 5] = (float)ti5;  outW[base + 5] = w5 * inv;

    float mg = v2 - v3;
    mg = fminf(mg, tv0 - tv1);
    mg = fminf(mg, tv1 - tv2);
    mg = fminf(mg, tv2 - tv3);
    mg = fminf(mg, tv3 - tv4);
    mg = fminf(mg, tv4 - tv5);
    mg = fminf(mg, tv5 - tv6);
    return mg;
}

extern "C" __global__ void __launch_bounds__(NTHREADS, 2)
moe_gate_kernel(const float* __restrict__ X,
                float* __restrict__ out, int T)
{
    extern __shared__ char smem[];
    float* logits = (float*)smem;
    const uint32_t sbase = smem_u32(smem);
    const uint32_t bar0 = sbase + MBAR_OFF;
    const uint32_t bar1 = sbase + MBAR_OFF + 8;

    const int tid  = threadIdx.x;
    const int wid  = tid >> 5;
    const int lane = tid & 31;
    const int wm   = wid >> 2;     // 0..1 : 32 token rows each
    const int wn   = wid & 3;      // 0..3 : 40 expert cols
    const int row0 = blockIdx.x * BM;

    if (tid == 0) {
        mbar_init(bar0, 1);
        mbar_init(bar1, 1);
    }
    __syncthreads();

    float acc[2][5][4];
#pragma unroll
    for (int i = 0; i < 2; i++)
#pragma unroll
        for (int j = 0; j < 5; j++)
#pragma unroll
            for (int r = 0; r < 4; r++) acc[i][j][r] = 0.0f;

    // A gmem: 64 rows x 32 k = 512 float4 per iter -> 2 per thread
    const int a0r = tid >> 3, a0q = tid & 7;         // rows 0..31
    const int a1r = a0r + 32, a1q = a0q;             // rows 32..63
    const float* Ap0 = X + (size_t)(row0 + a0r) * HIDDEN + a0q * 4;
    const float* Ap1 = X + (size_t)(row0 + a1r) * HIDDEN + a1q * 4;

    const char* W2 = (const char*)g_W2;

    // prologue: B(0,1) via single bulk copy
    if (tid == 0) {
        mbar_expect_tx(bar0, B_BYTES);
        bulk_cp(sbase + A_BYTES, W2, B_BYTES, bar0);
    }
    float4 fa0 = *(const float4*)(Ap0);
    float4 fa1 = *(const float4*)(Ap1);

    for (int it = 0; it < NITER; ++it) {
        char* buf = smem + (it & 1) * STAGE_BYTES;

        stage_f4A32(buf, a0r, a0q, fa0);
        stage_f4A32(buf, a1r, a1q, fa1);

        if (it + 1 < NITER) {
            const int k0 = (it + 1) * BKI;
            fa0 = *(const float4*)(Ap0 + k0);
            fa1 = *(const float4*)(Ap1 + k0);
        }

        // all warps past compute(it-1); A(it) visible after this
        __syncthreads();

        // issue B(it+1) into the other stage
        if (it + 1 < NITER && tid == 0) {
            const uint32_t b = ((it + 1) & 1) ? bar1 : bar0;
            mbar_expect_tx(b, B_BYTES);
            bulk_cp(sbase + ((it + 1) & 1) * STAGE_BYTES + A_BYTES,
                    W2 + (size_t)(it + 1) * B_BYTES, B_BYTES, b);
        }

        // wait B(it)
        mbar_wait((it & 1) ? bar1 : bar0, (it >> 1) & 1);

        // compute: 2 k16 halves, 3 split terms each
#pragma unroll
        for (int h = 0; h < 2; h++) {
            const char* ab = buf + h * 4096;
            const char* bb = buf + A_BYTES + h * B_IMG;

            uint4 bf[5];
#pragma unroll
            for (int j = 0; j < 5; j++)
                bf[j] = *(const uint4*)(bb + (wn * 5 + j) * 512 + lane * 16);

            uint4 ah[2], al[2];
#pragma unroll
            for (int i = 0; i < 2; i++) {
                const char* tb = ab + (wm * 2 + i) * 1024 + lane * 16;
                ah[i] = *(const uint4*)(tb);
                al[i] = *(const uint4*)(tb + 512);
            }

#pragma unroll
            for (int i = 0; i < 2; i++) {
                const uint32_t ar[4] = {ah[i].x, ah[i].y, ah[i].z, ah[i].w};
#pragma unroll
                for (int j = 0; j < 5; j++)
                    mma_bf16(acc[i][j], ar, bf[j].x, bf[j].y);   // hi*hi
            }
#pragma unroll
            for (int i = 0; i < 2; i++) {
                const uint32_t ar[4] = {ah[i].x, ah[i].y, ah[i].z, ah[i].w};
#pragma unroll
                for (int j = 0; j < 5; j++)
                    mma_bf16(acc[i][j], ar, bf[j].z, bf[j].w);   // hi*lo
            }
#pragma unroll
            for (int i = 0; i < 2; i++) {
                const uint32_t ar[4] = {al[i].x, al[i].y, al[i].z, al[i].w};
#pragma unroll
                for (int j = 0; j < 5; j++)
                    mma_bf16(acc[i][j], ar, bf[j].x, bf[j].y);   // lo*hi
            }
        }
    }

    __syncthreads();
    {
        const int g = lane >> 2, t = lane & 3;
#pragma unroll
        for (int i = 0; i < 2; i++) {
#pragma unroll
            for (int j = 0; j < 5; j++) {
                float* lrow = logits + (wm * 32 + i * 16 + g) * LSTR
                                     + wn * 40 + j * 8 + t * 2;
                lrow[0] = acc[i][j][0];
                lrow[1] = acc[i][j][1];
                lrow[8 * LSTR + 0] = acc[i][j][2];
                lrow[8 * LSTR + 1] = acc[i][j][3];
            }
        }
    }
    __syncthreads();

    if (tid < BM) {
        const int t = row0 + tid;
        if (t < T) {
            const float mg = do_gate(logits + tid * LSTR,
                                     out, out + (size_t)T * TOPK,
                                     (size_t)t * TOPK);
            if (mg < DELTA) {
                const int slot = atomicAdd(&g_count, 1);
                g_list[slot] = t;
            }
        }
    }
}

// ---- rescue v2 (verified): warp-parallel exact-fp32 recompute ----
extern "C" __global__ void __launch_bounds__(256, 1)
refine_kernel(const float* __restrict__ X,
              const float* __restrict__ W,
              float* __restrict__ out, int T)
{
    __shared__ float4 xs4[HIDDEN / 4];
    __shared__ float  lg[NEXP];

    const int tid  = threadIdx.x;
    const int wid  = tid >> 5;
    const int lane = tid & 31;

    const int count = g_count;
    for (int i = blockIdx.x; i < count; i += gridDim.x) {
        const int t = g_list[i];
        const float4* xr = (const float4*)(X + (size_t)t * HIDDEN);
#pragma unroll
        for (int j = 0; j < 5; j++)
            xs4[tid + j * 256] = xr[tid + j * 256];
        __syncthreads();

#pragma unroll 1
        for (int el = 0; el < EPG; el++) {
            const int e = wid * EPG + el;
            const float4* wr = (const float4*)(W + (size_t)e * HIDDEN);
            float s0 = 0.0f, s1 = 0.0f;
#pragma unroll
            for (int j = 0; j < 40; j += 2) {
                const float4 u0 = wr[lane + j * 32];
                const float4 x0 = xs4[lane + j * 32];
                s0 = fmaf(u0.x, x0.x, s0);
                s0 = fmaf(u0.y, x0.y, s0);
                s0 = fmaf(u0.z, x0.z, s0);
                s0 = fmaf(u0.w, x0.w, s0);
                const float4 u1 = wr[lane + (j + 1) * 32];
                const float4 x1 = xs4[lane + (j + 1) * 32];
                s1 = fmaf(u1.x, x1.x, s1);
                s1 = fmaf(u1.y, x1.y, s1);
                s1 = fmaf(u1.z, x1.z, s1);
                s1 = fmaf(u1.w, x1.w, s1);
            }
            float s = s0 + s1;
#pragma unroll
            for (int off = 16; off > 0; off >>= 1)
                s += __shfl_xor_sync(0xFFFFFFFFu, s, off);
            if (lane == 0) lg[e] = s;
        }
        __syncthreads();

        if (tid == 0)
            do_gate(lg, out, out + (size_t)T * TOPK, (size_t)t * TOPK);
        __syncthreads();
    }
}

extern "C" void kernel_launch(void* const* d_in, const int* in_sizes, int n_in,
                              void* d_out, int out_size)
{
    const float* X = (const float*)d_in[0];
    const float* W = (const float*)d_in[1];
    const int T = in_sizes[0] / HIDDEN;   // 16384

    cudaFuncSetAttribute(moe_gate_kernel,
                         cudaFuncAttributeMaxDynamicSharedMemorySize, SMEM_BYTES);

    prep_kernel<<<((HIDDEN / 16) * NEXP * 4 + 255) / 256, 256>>>(W);
    const int grid = (T + BM - 1) / BM;   // 256
    moe_gate_kernel<<<grid, NTHREADS, SMEM_BYTES>>>(X, (float*)d_out, T);
    refine_kernel<<<148, 256>>>(X, W, (float*)d_out, T);
}